// round 9
// baseline (speedup 1.0000x reference)
#include <cuda_runtime.h>

// QWT collapses: filt(x,h) = x * sum(h) (scalar), downsample is linear.
// Every output sub-band = coef * D, D = bicubic stride-2 downsample of image.
// Inputs: image (16,3,512,512) f32, gl/gh/fl/fh (30 f32 each)
// Output: concat of 4 tensors, each (16,12,256,256) f32.
//
// NOTE: filter sums MUST be computed sequentially (k=0..29) — Σgh/Σfl/Σfh are
// cancellation sums ~0 whose fp32 value depends on summation order. The sum
// loop is `#pragma unroll 1` so it stays order-exact AND doesn't inflate
// register allocation (R6 lesson).
//
// PERSISTENT: grid = 152 SMs * 7 resident blocks (smem 28.7KB/block -> 7/SM).
// Each block grid-strides over the 3072 (row-group, image) tiles: no wave
// quantization tail, coefs computed once per block.

#define W0 (-0.09375f)
#define W1 ( 0.59375f)
#define W2 ( 0.59375f)
#define W3 (-0.09375f)

#define N_TILES   3072          // 64 row-groups * 48 images
#define N_BLOCKS  1064          // 152 * 7

__global__ __launch_bounds__(256, 7) void qwt_down_kernel(const float* __restrict__ img,
                                                          const float* __restrict__ gl,
                                                          const float* __restrict__ gh,
                                                          const float* __restrict__ fl,
                                                          const float* __restrict__ fh,
                                                          float* __restrict__ out) {
    __shared__ float srows[10][512];   // 10 staged source rows
    __shared__ float vrow[4][512];     // vertically-filtered rows
    __shared__ float sc[16];           // 16 sub-band coefficients

    const int tid = threadIdx.x;

    // ---- once per block: sequential (order-exact) filter sums + 16 coefs ----
    if (tid < 16) {
        float A = 0.f, B = 0.f, C = 0.f, D = 0.f;
#pragma unroll 1
        for (int k = 0; k < 30; k++) {
            A += gl[k]; B += gh[k]; C += fl[k]; D += fh[k];
        }
        int t = tid >> 2, q = tid & 3;
        float f1 = (t < 2)        ? ((q & 1) ? C : A) : ((q & 1) ? D : B);
        float f2 = ((t & 1) == 0) ? ((q & 2) ? C : A) : ((q & 2) ? D : B);
        sc[tid] = f1 * f2;
    }
    // sc is ordered before any B2 read by the first __syncthreads below.

    const int x = tid & 63;                 // output col base (stride-64)
    const int y = tid >> 6;                 // output row within tile

    for (int tile = blockIdx.x; tile < N_TILES; tile += N_BLOCKS) {
        const int i0   = (tile & 63) * 4;   // first output row of this tile
        const int imgi = tile >> 6;         // b*3 + c

        const float* src = img + (size_t)imgi * 512 * 512;

        // ---- Stage A: coalesced float4 staging of 10 source rows (clamped) ----
        const int r_base = 2 * i0 - 1;
#pragma unroll
        for (int l = 0; l < 5; l++) {
            int idx = tid + l * 256;        // 0..1279 (10 rows * 128 float4)
            int k   = idx >> 7;             // row slot 0..9
            int c4  = (idx & 127) << 2;     // col base
            int r   = min(511, max(0, r_base + k));
            *(float4*)&srows[k][c4] = *(const float4*)&src[r * 512 + c4];
        }
        __syncthreads();

        // ---- Stage B1: vertical 4-tap pass, float4, conflict-free ----
#pragma unroll
        for (int l = 0; l < 2; l++) {
            int idx = tid + l * 256;        // 0..511
            int yy  = idx >> 7;             // output row within tile 0..3
            int c4  = (idx & 127) << 2;
            float4 a = *(float4*)&srows[2 * yy + 0][c4];
            float4 b = *(float4*)&srows[2 * yy + 1][c4];
            float4 c = *(float4*)&srows[2 * yy + 2][c4];
            float4 d = *(float4*)&srows[2 * yy + 3][c4];
            float4 v;
            v.x = W0 * a.x + W1 * b.x + W2 * c.x + W3 * d.x;
            v.y = W0 * a.y + W1 * b.y + W2 * c.y + W3 * d.y;
            v.z = W0 * a.z + W1 * b.z + W2 * c.z + W3 * d.z;
            v.w = W0 * a.w + W1 * b.w + W2 * c.w + W3 * d.w;
            *(float4*)&vrow[yy][c4] = v;
        }
        __syncthreads();

        // ---- Stage B2: horizontal pass + 16 scaled fan-out stores ----
        const int i = i0 + y;

        float d[4];
#pragma unroll
        for (int m = 0; m < 4; m++) {
            int j  = x + 64 * m;
            int c0 = max(0, 2 * j - 1);
            int c3 = min(511, 2 * j + 2);
            d[m] = W0 * vrow[y][c0] + W1 * vrow[y][2 * j]
                 + W2 * vrow[y][2 * j + 1] + W3 * vrow[y][c3];
        }

        const int b = imgi / 3;
        const int c = imgi % 3;
        // out[t][b, q*3+c, i, j]  with tensor size 16*12*256*256
        float* p = out + ((size_t)(b * 12 + c) * 256 + i) * 256 + x;

#pragma unroll
        for (int t = 0; t < 4; t++) {
            float* pt = p + (size_t)t * (16 * 12 * 256 * 256);
#pragma unroll
            for (int q = 0; q < 4; q++) {
                float s = sc[t * 4 + q];
#pragma unroll
                for (int m = 0; m < 4; m++)
                    __stcs(&pt[q * (3 * 256 * 256) + m * 64], s * d[m]);
            }
        }

        // protect srows/vrow before next tile's Stage A overwrites them
        __syncthreads();
    }
}

extern "C" void kernel_launch(void* const* d_in, const int* in_sizes, int n_in,
                              void* d_out, int out_size) {
    const float* image = (const float*)d_in[0];
    const float* gl    = (const float*)d_in[1];
    const float* gh    = (const float*)d_in[2];
    const float* fl    = (const float*)d_in[3];
    const float* fh    = (const float*)d_in[4];
    float* out = (float*)d_out;

    qwt_down_kernel<<<N_BLOCKS, 256>>>(image, gl, gh, fl, fh, out);
}

// round 10
// speedup vs baseline: 1.1486x; 1.1486x over previous
#include <cuda_runtime.h>

// QWT collapses: filt(x,h) = x * sum(h) (scalar), downsample is linear.
// Every output sub-band = coef * D, D = bicubic stride-2 downsample of image.
// Inputs: image (16,3,512,512) f32, gl/gh/fl/fh (30 f32 each)
// Output: concat of 4 tensors, each (16,12,256,256) f32.
//
// NOTE: filter sums MUST be computed sequentially (k=0..29) — Σgh/Σfl/Σfh are
// cancellation sums ~0 whose fp32 value depends on summation order. The sum
// loop is `#pragma unroll 1` so it stays order-exact AND doesn't inflate
// register allocation (R6 lesson). Persistent-loop variant regressed (R9:
// barrier coupling), so this is plain 3072-block launch.
//
// Structure: vertical 4-tap pass fused with the global loads (coalesced
// float4, rows hit L1/L2 on overlap) -> vrow smem -> horizontal pass ->
// 16 scaled streaming stores. Single __syncthreads per block.

#define W0 (-0.09375f)
#define W1 ( 0.59375f)
#define W2 ( 0.59375f)
#define W3 (-0.09375f)

// 256 threads/block. Block: 4 output rows x 256 cols of one image.
// Grid: (64 row-groups, 48 images).
__global__ __launch_bounds__(256, 8) void qwt_down_kernel(const float* __restrict__ img,
                                                          const float* __restrict__ gl,
                                                          const float* __restrict__ gh,
                                                          const float* __restrict__ fl,
                                                          const float* __restrict__ fh,
                                                          float* __restrict__ out) {
    __shared__ float vrow[4][512];     // vertically-filtered rows
    __shared__ float sc[16];           // 16 sub-band coefficients

    const int tid  = threadIdx.x;
    const int i0   = blockIdx.x * 4;   // first output row of this block
    const int imgi = blockIdx.y;       // b*3 + c

    // ---- threads 0..15: sequential (order-exact) filter sums + coefs ----
    if (tid < 16) {
        float A = 0.f, B = 0.f, C = 0.f, D = 0.f;
#pragma unroll 1
        for (int k = 0; k < 30; k++) {
            A += gl[k]; B += gh[k]; C += fl[k]; D += fh[k];
        }
        int t = tid >> 2, q = tid & 3;
        float f1 = (t < 2)        ? ((q & 1) ? C : A) : ((q & 1) ? D : B);
        float f2 = ((t & 1) == 0) ? ((q & 2) ? C : A) : ((q & 2) ? D : B);
        sc[tid] = f1 * f2;
    }

    const float* src = img + (size_t)imgi * 512 * 512;

    // ---- Stage V: vertical 4-tap pass fused with coalesced global loads ----
#pragma unroll
    for (int l = 0; l < 2; l++) {
        int idx = tid + l * 256;            // 0..511 (4 rows * 128 float4)
        int yy  = idx >> 7;                 // output row within block 0..3
        int c4  = (idx & 127) << 2;         // col base
        int i   = i0 + yy;
        int rb  = 2 * i - 1;
        int r0  = max(0, rb);               // clamp top edge
        int r3  = min(511, rb + 3);         // clamp bottom edge
        float4 a = *(const float4*)&src[(size_t)r0 * 512 + c4];
        float4 b = *(const float4*)&src[(size_t)(rb + 1) * 512 + c4];
        float4 c = *(const float4*)&src[(size_t)(rb + 2) * 512 + c4];
        float4 d = *(const float4*)&src[(size_t)r3 * 512 + c4];
        float4 v;
        v.x = W0 * a.x + W1 * b.x + W2 * c.x + W3 * d.x;
        v.y = W0 * a.y + W1 * b.y + W2 * c.y + W3 * d.y;
        v.z = W0 * a.z + W1 * b.z + W2 * c.z + W3 * d.z;
        v.w = W0 * a.w + W1 * b.w + W2 * c.w + W3 * d.w;
        *(float4*)&vrow[yy][c4] = v;
    }
    __syncthreads();

    // ---- Stage H: horizontal pass + 16 scaled fan-out stores (stride-64) ----
    const int x = tid & 63;                 // output col base
    const int y = tid >> 6;                 // output row within block
    const int i = i0 + y;

    float d[4];
#pragma unroll
    for (int m = 0; m < 4; m++) {
        int j  = x + 64 * m;
        int c0 = max(0, 2 * j - 1);
        int c3 = min(511, 2 * j + 2);
        d[m] = W0 * vrow[y][c0] + W1 * vrow[y][2 * j]
             + W2 * vrow[y][2 * j + 1] + W3 * vrow[y][c3];
    }

    const int b = imgi / 3;
    const int c = imgi % 3;
    // out[t][b, q*3+c, i, j]  with tensor size 16*12*256*256
    float* p = out + ((size_t)(b * 12 + c) * 256 + i) * 256 + x;

#pragma unroll
    for (int t = 0; t < 4; t++) {
        float* pt = p + (size_t)t * (16 * 12 * 256 * 256);
#pragma unroll
        for (int q = 0; q < 4; q++) {
            float s = sc[t * 4 + q];
#pragma unroll
            for (int m = 0; m < 4; m++)
                __stcs(&pt[q * (3 * 256 * 256) + m * 64], s * d[m]);
        }
    }
}

extern "C" void kernel_launch(void* const* d_in, const int* in_sizes, int n_in,
                              void* d_out, int out_size) {
    const float* image = (const float*)d_in[0];
    const float* gl    = (const float*)d_in[1];
    const float* gh    = (const float*)d_in[2];
    const float* fl    = (const float*)d_in[3];
    const float* fh    = (const float*)d_in[4];
    float* out = (float*)d_out;

    dim3 block(256, 1, 1);
    dim3 grid(64, 48, 1);
    qwt_down_kernel<<<grid, block>>>(image, gl, gh, fl, fh, out);
}